// round 3
// baseline (speedup 1.0000x reference)
#include <cuda_runtime.h>
#include <cuda_bf16.h>
#include <math.h>

// Problem constants
#define BATCH 32
#define LMAX  4096
#define KD    256     // D
#define N3    768     // 3*D

// Scratch (device globals; allocation-free)
__device__ float g_gi [ (size_t)BATCH * LMAX        * N3 ];  // gi for all nodes of current level
__device__ float g_gh [ (size_t)BATCH * (LMAX/2)   * N3 ];  // gh for current half-level
__device__ float g_h1 [ (size_t)BATCH * (LMAX/2)   * KD ];  // h1 per pair
__device__ float g_emb[ (size_t)BATCH * (LMAX/2)   * KD ];  // embeds for next level
__device__ float g_hs [ (size_t)BATCH * (LMAX/2)   * KD ];  // hs for next level

enum { MODE_DIRECT = 0, MODE_STRIDED = 1, MODE_PAIRAVG = 2 };

// C[M, 768] = A[M, 256] @ W[768,256]^T + bias
// A-row gather depends on mode:
//   DIRECT : A row gr at Asrc + gr*256
//   STRIDED: gr -> (b = gr/n_nodes, j = gr%n_nodes), Asrc + (b*src_stride + j)*256
//   PAIRAVG: gr -> (b = gr/pairs, p), 0.5*(row(b,2p) + row(b,2p+1)) of Asrc w/ stride
__global__ __launch_bounds__(256)
void gemm_kernel(const float* __restrict__ Asrc,
                 const float* __restrict__ W,
                 const float* __restrict__ bias,
                 float* __restrict__ C,
                 int M, int n_nodes, int src_stride, int mode)
{
    __shared__ float As[32][68];
    __shared__ float Ws[32][68];

    const int tid  = threadIdx.x;
    const int row0 = blockIdx.x * 64;
    const int col0 = blockIdx.y * 64;

    const int lr = tid >> 3;          // 0..31
    const int lk = (tid & 7) * 4;     // 0,4,...,28

    // Resolve per-row global pointers once
    const float* aptrA[2];
    const float* aptrB[2];
    bool valid[2];
#pragma unroll
    for (int i = 0; i < 2; i++) {
        int gr = row0 + lr + i * 32;
        valid[i] = (gr < M);
        aptrA[i] = nullptr; aptrB[i] = nullptr;
        if (valid[i]) {
            if (mode == MODE_DIRECT) {
                aptrA[i] = Asrc + (size_t)gr * KD;
            } else if (mode == MODE_STRIDED) {
                int b = gr / n_nodes;
                int j = gr - b * n_nodes;
                aptrA[i] = Asrc + ((size_t)b * src_stride + j) * KD;
            } else { // PAIRAVG
                int pairs = n_nodes >> 1;
                int b = gr / pairs;
                int p = gr - b * pairs;
                const float* base = Asrc + ((size_t)b * src_stride + 2 * p) * KD;
                aptrA[i] = base;
                aptrB[i] = base + KD;
            }
        }
    }
    const float* wptr[2];
#pragma unroll
    for (int i = 0; i < 2; i++) {
        int gc = col0 + lr + i * 32;   // always < 768
        wptr[i] = W + (size_t)gc * KD;
    }

    float acc[4][4];
#pragma unroll
    for (int i = 0; i < 4; i++)
#pragma unroll
        for (int j = 0; j < 4; j++) acc[i][j] = 0.f;

    const int tm = (tid >> 4) * 4;    // 0..60
    const int tn = (tid & 15) * 4;    // 0..60

    for (int kt = 0; kt < KD; kt += 32) {
#pragma unroll
        for (int i = 0; i < 2; i++) {
            int rr = lr + i * 32;
            float4 a = make_float4(0.f, 0.f, 0.f, 0.f);
            if (valid[i]) {
                a = *(const float4*)(aptrA[i] + kt + lk);
                if (mode == MODE_PAIRAVG) {
                    float4 b4 = *(const float4*)(aptrB[i] + kt + lk);
                    a.x = 0.5f * (a.x + b4.x);
                    a.y = 0.5f * (a.y + b4.y);
                    a.z = 0.5f * (a.z + b4.z);
                    a.w = 0.5f * (a.w + b4.w);
                }
            }
            As[lk + 0][rr] = a.x; As[lk + 1][rr] = a.y;
            As[lk + 2][rr] = a.z; As[lk + 3][rr] = a.w;

            float4 w4 = *(const float4*)(wptr[i] + kt + lk);
            Ws[lk + 0][rr] = w4.x; Ws[lk + 1][rr] = w4.y;
            Ws[lk + 2][rr] = w4.z; Ws[lk + 3][rr] = w4.w;
        }
        __syncthreads();

#pragma unroll
        for (int k = 0; k < 32; k++) {
            float4 av = *(const float4*)&As[k][tm];
            float4 wv = *(const float4*)&Ws[k][tn];
            acc[0][0] += av.x * wv.x; acc[0][1] += av.x * wv.y;
            acc[0][2] += av.x * wv.z; acc[0][3] += av.x * wv.w;
            acc[1][0] += av.y * wv.x; acc[1][1] += av.y * wv.y;
            acc[1][2] += av.y * wv.z; acc[1][3] += av.y * wv.w;
            acc[2][0] += av.z * wv.x; acc[2][1] += av.z * wv.y;
            acc[2][2] += av.z * wv.z; acc[2][3] += av.z * wv.w;
            acc[3][0] += av.w * wv.x; acc[3][1] += av.w * wv.y;
            acc[3][2] += av.w * wv.z; acc[3][3] += av.w * wv.w;
        }
        __syncthreads();
    }

    float4 bv = *(const float4*)&bias[col0 + tn];
#pragma unroll
    for (int i = 0; i < 4; i++) {
        int gr = row0 + tm + i;
        if (gr < M) {
            float4 o;
            o.x = acc[i][0] + bv.x;
            o.y = acc[i][1] + bv.y;
            o.z = acc[i][2] + bv.z;
            o.w = acc[i][3] + bv.w;
            *(float4*)&C[(size_t)gr * N3 + col0 + tn] = o;
        }
    }
}

__device__ __forceinline__ float sigmoidf_(float x) { return 1.0f / (1.0f + expf(-x)); }

// h1 = GRU(x_L via gi, h0). If gh==null: gh := b_hh (level-1, h0==0). If hs==null: h0 = 0.
__global__ __launch_bounds__(256)
void pw1_kernel(const float* __restrict__ gi,
                const float* __restrict__ gh,
                const float* __restrict__ b_hh,
                const float* __restrict__ hs,
                float* __restrict__ h1,
                int pairs, int n_nodes)
{
    int t = blockIdx.x * 256 + threadIdx.x;
    int r = t >> 8;
    int k = t & 255;
    int b = r / pairs;
    int p = r - b * pairs;

    size_t giL = ((size_t)b * n_nodes + 2 * p) * N3;
    float ir  = gi[giL + k];
    float iz  = gi[giL + 256 + k];
    float inn = gi[giL + 512 + k];

    float hr, hz, hn;
    if (gh) {
        size_t g = (size_t)r * N3;
        hr = gh[g + k]; hz = gh[g + 256 + k]; hn = gh[g + 512 + k];
    } else {
        hr = b_hh[k]; hz = b_hh[256 + k]; hn = b_hh[512 + k];
    }

    float h0 = 0.f;
    if (hs) {
        size_t hb = ((size_t)b * (LMAX / 2) + 2 * p) * KD + k;
        h0 = 0.5f * (hs[hb] + hs[hb + KD]);
    }

    float rg = sigmoidf_(ir + hr);
    float zg = sigmoidf_(iz + hz);
    float ng = tanhf(inn + rg * hn);
    h1[(size_t)r * KD + k] = (1.f - zg) * ng + zg * h0;
}

// h2 = GRU(x_R via gi, h1); emb = 0.5*(h1+h2); hs = h2; optional final output write.
__global__ __launch_bounds__(256)
void pw2_kernel(const float* __restrict__ gi,
                const float* __restrict__ gh,
                const float* __restrict__ h1,
                float* __restrict__ emb,
                float* __restrict__ hs,
                float* __restrict__ outp,
                int pairs, int n_nodes, int write_out)
{
    int t = blockIdx.x * 256 + threadIdx.x;
    int r = t >> 8;
    int k = t & 255;
    int b = r / pairs;
    int p = r - b * pairs;

    size_t giR = ((size_t)b * n_nodes + 2 * p + 1) * N3;
    size_t g   = (size_t)r * N3;
    float ir  = gi[giR + k];
    float iz  = gi[giR + 256 + k];
    float inn = gi[giR + 512 + k];
    float hr  = gh[g + k];
    float hz  = gh[g + 256 + k];
    float hn  = gh[g + 512 + k];
    float hp  = h1[(size_t)r * KD + k];

    float rg = sigmoidf_(ir + hr);
    float zg = sigmoidf_(iz + hz);
    float ng = tanhf(inn + rg * hn);
    float h2 = (1.f - zg) * ng + zg * hp;

    size_t o = ((size_t)b * (LMAX / 2) + p) * KD + k;
    float e  = 0.5f * (hp + h2);
    emb[o] = e;
    hs[o]  = h2;
    if (write_out) outp[(size_t)b * KD + k] = e;
}

extern "C" void kernel_launch(void* const* d_in, const int* in_sizes, int n_in,
                              void* d_out, int out_size)
{
    const float* leaf = (const float*)d_in[0];
    const float* W_ih = (const float*)d_in[1];
    const float* W_hh = (const float*)d_in[2];
    const float* b_ih = (const float*)d_in[3];
    const float* b_hh = (const float*)d_in[4];
    float* out = (float*)d_out;

    float *gi, *gh, *h1, *emb, *hs;
    cudaGetSymbolAddress((void**)&gi,  g_gi);
    cudaGetSymbolAddress((void**)&gh,  g_gh);
    cudaGetSymbolAddress((void**)&h1,  g_h1);
    cudaGetSymbolAddress((void**)&emb, g_emb);
    cudaGetSymbolAddress((void**)&hs,  g_hs);

    const float* src = leaf;
    int stride = LMAX;

    for (int n = LMAX; n > 1; n >>= 1) {
        int pairs = n >> 1;
        int Mfull = BATCH * n;
        int Mhalf = BATCH * pairs;

        // gi for all nodes of this level
        {
            dim3 grid((Mfull + 63) / 64, 12);
            gemm_kernel<<<grid, 256>>>(src, W_ih, b_ih, gi, Mfull, n, stride, MODE_STRIDED);
        }

        if (n == LMAX) {
            // level 1: hs == 0 -> h0 == 0, gh1 == b_hh (no GEMM needed)
            pw1_kernel<<<Mhalf, 256>>>(gi, nullptr, b_hh, nullptr, h1, pairs, n);
        } else {
            dim3 grid((Mhalf + 63) / 64, 12);
            gemm_kernel<<<grid, 256>>>(hs, W_hh, b_hh, gh, Mhalf, n, LMAX / 2, MODE_PAIRAVG);
            pw1_kernel<<<Mhalf, 256>>>(gi, gh, nullptr, hs, h1, pairs, n);
        }

        // gh2 = h1 @ W_hh^T + b_hh
        {
            dim3 grid((Mhalf + 63) / 64, 12);
            gemm_kernel<<<grid, 256>>>(h1, W_hh, b_hh, gh, Mhalf, 0, 0, MODE_DIRECT);
        }

        pw2_kernel<<<Mhalf, 256>>>(gi, gh, h1, emb, hs, out,
                                   pairs, n, (pairs == 1) ? 1 : 0);

        src = emb;
        stride = LMAX / 2;
    }
}

// round 6
// speedup vs baseline: 2.4174x; 2.4174x over previous
#include <cuda_runtime.h>
#include <cuda_bf16.h>
#include <math.h>
#include <stdint.h>

#define BATCH 32
#define LMAX  4096
#define KD    256
#define N3    768

// ---------------- device scratch (allocation-free) ----------------
__device__ float g_gi [(size_t)BATCH*LMAX*N3];
__device__ float g_gh [(size_t)BATCH*(LMAX/2)*N3];
__device__ float g_h1f[(size_t)BATCH*(LMAX/2)*KD];
__device__ float g_h0f[(size_t)BATCH*(LMAX/2)*KD];
__device__ float g_hs [(size_t)BATCH*(LMAX/2)*KD];

__device__ __nv_bfloat16 g_Ahi[(size_t)BATCH*LMAX*KD];
__device__ __nv_bfloat16 g_Alo[(size_t)BATCH*LMAX*KD];
__device__ __nv_bfloat16 g_h0hi[(size_t)BATCH*(LMAX/2)*KD];
__device__ __nv_bfloat16 g_h0lo[(size_t)BATCH*(LMAX/2)*KD];
__device__ __nv_bfloat16 g_h1hi[(size_t)BATCH*(LMAX/2)*KD];
__device__ __nv_bfloat16 g_h1lo[(size_t)BATCH*(LMAX/2)*KD];
__device__ __nv_bfloat16 g_Wih_hi[N3*KD];
__device__ __nv_bfloat16 g_Wih_lo[N3*KD];
__device__ __nv_bfloat16 g_Whh_hi[N3*KD];
__device__ __nv_bfloat16 g_Whh_lo[N3*KD];

__device__ __forceinline__ uint32_t smem_u32(const void* p) {
    uint32_t a;
    asm("{ .reg .u64 t; cvta.to.shared.u64 t, %1; cvt.u32.u64 %0, t; }" : "=r"(a) : "l"(p));
    return a;
}

// ================= bf16-split GEMM on mma.sync (legacy HMMA) =================
// C[M,768] = A[M,256] @ W[768,256]^T + bias, computed as one K'=768 GEMM:
//   A' = [Ahi | Ahi | Alo],  W' = [Whi | Wlo | Whi]   (address-mapped, fp32 acc)
// CTA: 128 rows x 128 cols (blockIdx.y = N-chunk 0..5). 8 warps (2x4), warp 64x32.
// K chunks of 64, cp.async double-buffered, XOR-swizzled SMEM, ldmatrix + 16816 mma.

#define GEMM_SMEM (2*32768)

__global__ void __launch_bounds__(256, 2)
gemm_mma(const __nv_bfloat16* __restrict__ Ahi, const __nv_bfloat16* __restrict__ Alo,
         const __nv_bfloat16* __restrict__ Whi, const __nv_bfloat16* __restrict__ Wlo,
         const float* __restrict__ bias, float* __restrict__ C, int M)
{
    extern __shared__ char smem[];
    const int tid  = threadIdx.x;
    const int lane = tid & 31;
    const int wid  = tid >> 5;
    const int wm   = wid >> 2;          // 0..1  (64 rows each)
    const int wn   = wid & 3;           // 0..3  (32 cols each)
    const int row0 = blockIdx.x * 128;
    const int nc   = blockIdx.y;        // 0..5

    float acc[4][4][4];
    #pragma unroll
    for (int t = 0; t < 4; t++)
        #pragma unroll
        for (int n = 0; n < 4; n++)
            #pragma unroll
            for (int i = 0; i < 4; i++) acc[t][n][i] = 0.f;

    // ---- chunk loader: chunk c (64 k' values) into buffer buf ----
    auto load_chunk = [&](int c, int buf) {
        const __nv_bfloat16* Asrc = (c < 8) ? Ahi : Alo;
        const __nv_bfloat16* Wsrc = (c < 4) ? Whi : ((c < 8) ? Wlo : Whi);
        const int kbase = (c & 3) * 64;
        char* sA = smem + buf * 32768;
        char* sB = sA + 16384;
        #pragma unroll
        for (int it = 0; it < 8; it++) {
            int i   = tid + it * 256;           // 0..2047
            int isB = i >> 10;
            int idx = i & 1023;
            int r   = idx >> 3;                 // 0..127
            int c8  = idx & 7;                  // 16B chunk within 128B row
            const __nv_bfloat16* src;
            char* dst;
            if (!isB) {
                int gr = row0 + r;
                if (gr >= M) gr = M - 1;        // clamp (stores are guarded)
                src = Asrc + (size_t)gr * KD + kbase + c8 * 8;
                dst = sA + r * 128 + ((c8 ^ (r & 7)) << 4);
            } else {
                int gn = nc * 128 + r;          // always < 768
                src = Wsrc + (size_t)gn * KD + kbase + c8 * 8;
                dst = sB + r * 128 + ((c8 ^ (r & 7)) << 4);
            }
            uint32_t d32 = smem_u32(dst);
            asm volatile("cp.async.cg.shared.global [%0], [%1], 16;"
                         :: "r"(d32), "l"(src));
        }
    };

    load_chunk(0, 0);
    asm volatile("cp.async.commit_group;" ::: "memory");

    for (int c = 0; c < 12; c++) {
        const int buf = c & 1;
        if (c + 1 < 12) {
            load_chunk(c + 1, buf ^ 1);
            asm volatile("cp.async.commit_group;" ::: "memory");
            asm volatile("cp.async.wait_group 1;" ::: "memory");
        } else {
            asm volatile("cp.async.wait_group 0;" ::: "memory");
        }
        __syncthreads();

        char* sA = smem + buf * 32768;
        char* sB = sA + 16384;

        #pragma unroll
        for (int s = 0; s < 4; s++) {           // k16 steps within 64-chunk
            uint32_t a[4][4];
            #pragma unroll
            for (int t = 0; t < 4; t++) {
                int row = wm * 64 + t * 16 + (lane & 15);
                int c8  = s * 2 + (lane >> 4);
                uint32_t ad = smem_u32(sA + row * 128 + ((c8 ^ (row & 7)) << 4));
                asm volatile("ldmatrix.sync.aligned.m8n8.x4.shared.b16 {%0,%1,%2,%3}, [%4];"
                             : "=r"(a[t][0]), "=r"(a[t][1]), "=r"(a[t][2]), "=r"(a[t][3])
                             : "r"(ad));
            }
            uint32_t b[2][4];
            #pragma unroll
            for (int q = 0; q < 2; q++) {
                int nrow = wn * 32 + q * 16 + (lane & 7) + ((lane & 16) >> 1);
                int c8   = s * 2 + ((lane >> 3) & 1);
                uint32_t ad = smem_u32(sB + nrow * 128 + ((c8 ^ (nrow & 7)) << 4));
                asm volatile("ldmatrix.sync.aligned.m8n8.x4.shared.b16 {%0,%1,%2,%3}, [%4];"
                             : "=r"(b[q][0]), "=r"(b[q][1]), "=r"(b[q][2]), "=r"(b[q][3])
                             : "r"(ad));
            }
            #pragma unroll
            for (int t = 0; t < 4; t++) {
                #pragma unroll
                for (int nt = 0; nt < 4; nt++) {
                    uint32_t b0 = b[nt >> 1][(nt & 1) * 2 + 0];
                    uint32_t b1 = b[nt >> 1][(nt & 1) * 2 + 1];
                    asm volatile(
                        "mma.sync.aligned.m16n8k16.row.col.f32.bf16.bf16.f32 "
                        "{%0,%1,%2,%3}, {%4,%5,%6,%7}, {%8,%9}, {%0,%1,%2,%3};"
                        : "+f"(acc[t][nt][0]), "+f"(acc[t][nt][1]),
                          "+f"(acc[t][nt][2]), "+f"(acc[t][nt][3])
                        : "r"(a[t][0]), "r"(a[t][1]), "r"(a[t][2]), "r"(a[t][3]),
                          "r"(b0), "r"(b1));
                }
            }
        }
        __syncthreads();
    }

    // ---- epilogue: add bias, store fp32 ----
    const int gq = lane >> 2;
    const int tg = lane & 3;
    #pragma unroll
    for (int t = 0; t < 4; t++) {
        int row = row0 + wm * 64 + t * 16 + gq;
        #pragma unroll
        for (int nt = 0; nt < 4; nt++) {
            int col = nc * 128 + wn * 32 + nt * 8 + tg * 2;
            float bx = bias[col], by = bias[col + 1];
            if (row < M) {
                float2 o = make_float2(acc[t][nt][0] + bx, acc[t][nt][1] + by);
                *(float2*)&C[(size_t)row * N3 + col] = o;
            }
            if (row + 8 < M) {
                float2 o = make_float2(acc[t][nt][2] + bx, acc[t][nt][3] + by);
                *(float2*)&C[(size_t)(row + 8) * N3 + col] = o;
            }
        }
    }
}

// ---------------- pointwise / conversion kernels ----------------
__device__ __forceinline__ float sigmoidf_(float x) { return 1.0f / (1.0f + expf(-x)); }
__device__ __forceinline__ void bf_split(float v, __nv_bfloat16* hi, __nv_bfloat16* lo, size_t i) {
    __nv_bfloat16 h = __float2bfloat16(v);
    hi[i] = h;
    lo[i] = __float2bfloat16(v - __bfloat162float(h));
}

__global__ void split_kernel(const float* __restrict__ x,
                             __nv_bfloat16* __restrict__ hi, __nv_bfloat16* __restrict__ lo,
                             size_t n)
{
    size_t i = (size_t)blockIdx.x * blockDim.x + threadIdx.x;
    if (i < n) bf_split(x[i], hi, lo, i);
}

__global__ __launch_bounds__(256)
void prep_kernel(const float* __restrict__ hs, float* __restrict__ h0f,
                 __nv_bfloat16* __restrict__ h0hi, __nv_bfloat16* __restrict__ h0lo,
                 int pairs, int n)
{
    int r = blockIdx.x, k = threadIdx.x;
    int b = r / pairs, p = r - b * pairs;
    size_t base = ((size_t)(b * n + 2 * p)) * KD + k;
    float h = 0.5f * (hs[base] + hs[base + KD]);
    size_t o = (size_t)r * KD + k;
    h0f[o] = h;
    bf_split(h, h0hi, h0lo, o);
}

__global__ __launch_bounds__(256)
void pw1_kernel(const float* __restrict__ gi, const float* __restrict__ gh,
                const float* __restrict__ b_hh, const float* __restrict__ h0f,
                float* __restrict__ h1f,
                __nv_bfloat16* __restrict__ h1hi, __nv_bfloat16* __restrict__ h1lo,
                int pairs, int n)
{
    int r = blockIdx.x, k = threadIdx.x;
    int b = r / pairs, p = r - b * pairs;
    size_t giL = ((size_t)(b * n + 2 * p)) * N3;
    float ir = gi[giL + k], iz = gi[giL + 256 + k], in_ = gi[giL + 512 + k];
    float hr, hz, hn;
    if (gh) {
        size_t g = (size_t)r * N3;
        hr = gh[g + k]; hz = gh[g + 256 + k]; hn = gh[g + 512 + k];
    } else {
        hr = b_hh[k]; hz = b_hh[256 + k]; hn = b_hh[512 + k];
    }
    float h0 = h0f ? h0f[(size_t)r * KD + k] : 0.f;
    float rg = sigmoidf_(ir + hr);
    float zg = sigmoidf_(iz + hz);
    float ng = tanhf(in_ + rg * hn);
    float h1 = (1.f - zg) * ng + zg * h0;
    size_t o = (size_t)r * KD + k;
    h1f[o] = h1;
    bf_split(h1, h1hi, h1lo, o);
}

__global__ __launch_bounds__(256)
void pw2_kernel(const float* __restrict__ gi, const float* __restrict__ gh,
                const float* __restrict__ h1f,
                float* __restrict__ hs,
                __nv_bfloat16* __restrict__ ehi, __nv_bfloat16* __restrict__ elo,
                float* __restrict__ outp,
                int pairs, int n, int write_out)
{
    int r = blockIdx.x, k = threadIdx.x;
    int b = r / pairs, p = r - b * pairs;
    size_t giR = ((size_t)(b * n + 2 * p + 1)) * N3;
    size_t g = (size_t)r * N3;
    float ir = gi[giR + k], iz = gi[giR + 256 + k], in_ = gi[giR + 512 + k];
    float hr = gh[g + k], hz = gh[g + 256 + k], hn = gh[g + 512 + k];
    float hp = h1f[(size_t)r * KD + k];
    float rg = sigmoidf_(ir + hr);
    float zg = sigmoidf_(iz + hz);
    float ng = tanhf(in_ + rg * hn);
    float h2 = (1.f - zg) * ng + zg * hp;
    float e = 0.5f * (hp + h2);
    size_t o = (size_t)r * KD + k;
    hs[o] = h2;
    bf_split(e, ehi, elo, o);
    if (write_out) outp[(size_t)b * KD + k] = e;
}

// ---------------- launcher ----------------
extern "C" void kernel_launch(void* const* d_in, const int* in_sizes, int n_in,
                              void* d_out, int out_size)
{
    const float* leaf = (const float*)d_in[0];
    const float* W_ih = (const float*)d_in[1];
    const float* W_hh = (const float*)d_in[2];
    const float* b_ih = (const float*)d_in[3];
    const float* b_hh = (const float*)d_in[4];
    float* out = (float*)d_out;

    float *gi, *gh, *h1f, *h0f, *hs;
    cudaGetSymbolAddress((void**)&gi,  g_gi);
    cudaGetSymbolAddress((void**)&gh,  g_gh);
    cudaGetSymbolAddress((void**)&h1f, g_h1f);
    cudaGetSymbolAddress((void**)&h0f, g_h0f);
    cudaGetSymbolAddress((void**)&hs,  g_hs);
    __nv_bfloat16 *Ahi, *Alo, *h0hi, *h0lo, *h1hi, *h1lo, *Wih_hi, *Wih_lo, *Whh_hi, *Whh_lo;
    cudaGetSymbolAddress((void**)&Ahi, g_Ahi);
    cudaGetSymbolAddress((void**)&Alo, g_Alo);
    cudaGetSymbolAddress((void**)&h0hi, g_h0hi);
    cudaGetSymbolAddress((void**)&h0lo, g_h0lo);
    cudaGetSymbolAddress((void**)&h1hi, g_h1hi);
    cudaGetSymbolAddress((void**)&h1lo, g_h1lo);
    cudaGetSymbolAddress((void**)&Wih_hi, g_Wih_hi);
    cudaGetSymbolAddress((void**)&Wih_lo, g_Wih_lo);
    cudaGetSymbolAddress((void**)&Whh_hi, g_Whh_hi);
    cudaGetSymbolAddress((void**)&Whh_lo, g_Whh_lo);

    cudaFuncSetAttribute(gemm_mma, cudaFuncAttributeMaxDynamicSharedMemorySize, GEMM_SMEM);

    {
        size_t nl = (size_t)BATCH * LMAX * KD;
        split_kernel<<<(unsigned)((nl + 255) / 256), 256>>>(leaf, Ahi, Alo, nl);
        size_t nw = (size_t)N3 * KD;
        split_kernel<<<(unsigned)((nw + 255) / 256), 256>>>(W_ih, Wih_hi, Wih_lo, nw);
        split_kernel<<<(unsigned)((nw + 255) / 256), 256>>>(W_hh, Whh_hi, Whh_lo, nw);
    }

    for (int n = LMAX; n > 1; n >>= 1) {
        int pairs = n >> 1;
        int Mf = BATCH * n;
        int Mh = BATCH * pairs;

        // gi = A @ W_ih^T + b_ih over all nodes of this level
        {
            dim3 grid((Mf + 127) / 128, 6);
            gemm_mma<<<grid, 256, GEMM_SMEM>>>(Ahi, Alo, Wih_hi, Wih_lo, b_ih, gi, Mf);
        }

        if (n == LMAX) {
            pw1_kernel<<<Mh, 256>>>(gi, nullptr, b_hh, nullptr, h1f, h1hi, h1lo, pairs, n);
        } else {
            prep_kernel<<<Mh, 256>>>(hs, h0f, h0hi, h0lo, pairs, n);
            dim3 grid((Mh + 127) / 128, 6);
            gemm_mma<<<grid, 256, GEMM_SMEM>>>(h0hi, h0lo, Whh_hi, Whh_lo, b_hh, gh, Mh);
            pw1_kernel<<<Mh, 256>>>(gi, gh, b_hh, h0f, h1f, h1hi, h1lo, pairs, n);
        }

        {
            dim3 grid((Mh + 127) / 128, 6);
            gemm_mma<<<grid, 256, GEMM_SMEM>>>(h1hi, h1lo, Whh_hi, Whh_lo, b_hh, gh, Mh);
        }

        pw2_kernel<<<Mh, 256>>>(gi, gh, h1f, hs, Ahi, Alo, out,
                                pairs, n, (pairs == 1) ? 1 : 0);
    }
}

// round 8
// speedup vs baseline: 2.5652x; 1.0611x over previous
#include <cuda_runtime.h>
#include <cuda_bf16.h>
#include <math.h>
#include <stdint.h>

#define BATCH 32
#define LMAX  4096
#define KD    256
#define N3    768

// ---------------- device scratch (allocation-free) ----------------
__device__ float g_gi [(size_t)BATCH*LMAX*N3];
__device__ float g_gh [(size_t)BATCH*(LMAX/2)*N3];
__device__ float g_h1f[(size_t)BATCH*(LMAX/2)*KD];
__device__ float g_h0f[(size_t)BATCH*(LMAX/2)*KD];

__device__ __nv_bfloat16 g_Ahi[(size_t)BATCH*LMAX*KD];
__device__ __nv_bfloat16 g_Alo[(size_t)BATCH*LMAX*KD];
__device__ __nv_bfloat16 g_h0hi[(size_t)BATCH*(LMAX/2)*KD];
__device__ __nv_bfloat16 g_h0lo[(size_t)BATCH*(LMAX/2)*KD];
__device__ __nv_bfloat16 g_h1hi[(size_t)BATCH*(LMAX/2)*KD];
__device__ __nv_bfloat16 g_h1lo[(size_t)BATCH*(LMAX/2)*KD];
__device__ __nv_bfloat16 g_Wih_hi[N3*KD];
__device__ __nv_bfloat16 g_Wih_lo[N3*KD];
__device__ __nv_bfloat16 g_Whh_hi[N3*KD];
__device__ __nv_bfloat16 g_Whh_lo[N3*KD];

__device__ __forceinline__ uint32_t smem_u32(const void* p) {
    uint32_t a;
    asm("{ .reg .u64 t; cvta.to.shared.u64 t, %1; cvt.u32.u64 %0, t; }" : "=r"(a) : "l"(p));
    return a;
}

// ================= bf16-split GEMM on mma.sync (legacy HMMA) =================
// C[M,768] = A[M,256] @ W[768,256]^T + bias as one K'=768 GEMM:
//   A' = [Ahi|Ahi|Alo],  W' = [Whi|Wlo|Whi]  (address-mapped), fp32 acc.
// CTA 128x128 (blockIdx.y = N-chunk 0..5); 8 warps (2x4), warp 64x32.
// 3-stage cp.async pipeline over 12 K-chunks of 64; XOR-swizzled SMEM;
// ldmatrix + mma.m16n8k16.bf16. blockIdx.z selects problem (gi vs gh1 fusion).

#define STAGES 3
#define GEMM_SMEM (STAGES*32768)

__global__ void __launch_bounds__(256, 2)
gemm_mma(const __nv_bfloat16* __restrict__ Ahi,  const __nv_bfloat16* __restrict__ Alo,
         const __nv_bfloat16* __restrict__ Whi,  const __nv_bfloat16* __restrict__ Wlo,
         const float* __restrict__ bias, float* __restrict__ C, int M,
         const __nv_bfloat16* A2hi, const __nv_bfloat16* A2lo,
         const __nv_bfloat16* W2hi, const __nv_bfloat16* W2lo,
         const float* bias2, float* C2, int M2)
{
    if (blockIdx.z == 1) {
        Ahi = A2hi; Alo = A2lo; Whi = W2hi; Wlo = W2lo;
        bias = bias2; C = C2; M = M2;
    }
    const int row0 = blockIdx.x * 128;
    if (row0 >= M) return;                      // uniform per-block exit (fused z=1 tail)

    extern __shared__ char smem[];
    const int tid  = threadIdx.x;
    const int lane = tid & 31;
    const int wid  = tid >> 5;
    const int wm   = wid >> 2;
    const int wn   = wid & 3;
    const int nc   = blockIdx.y;                // 0..5

    float acc[4][4][4];
    #pragma unroll
    for (int t = 0; t < 4; t++)
        #pragma unroll
        for (int n = 0; n < 4; n++)
            #pragma unroll
            for (int i = 0; i < 4; i++) acc[t][n][i] = 0.f;

    auto load_chunk = [&](int c, int buf) {
        const __nv_bfloat16* Asrc = (c < 8) ? Ahi : Alo;
        const __nv_bfloat16* Wsrc = (c < 4) ? Whi : ((c < 8) ? Wlo : Whi);
        const int kbase = (c & 3) * 64;
        char* sA = smem + buf * 32768;
        char* sB = sA + 16384;
        #pragma unroll
        for (int it = 0; it < 8; it++) {
            int i   = tid + it * 256;
            int isB = i >> 10;
            int idx = i & 1023;
            int r   = idx >> 3;
            int c8  = idx & 7;
            const __nv_bfloat16* src;
            char* dst;
            if (!isB) {
                int gr = row0 + r;
                if (gr >= M) gr = M - 1;
                src = Asrc + (size_t)gr * KD + kbase + c8 * 8;
                dst = sA + r * 128 + ((c8 ^ (r & 7)) << 4);
            } else {
                int gn = nc * 128 + r;
                src = Wsrc + (size_t)gn * KD + kbase + c8 * 8;
                dst = sB + r * 128 + ((c8 ^ (r & 7)) << 4);
            }
            uint32_t d32 = smem_u32(dst);
            asm volatile("cp.async.cg.shared.global [%0], [%1], 16;"
                         :: "r"(d32), "l"(src));
        }
    };

    // prologue: 2 chunks in flight
    load_chunk(0, 0);
    asm volatile("cp.async.commit_group;" ::: "memory");
    load_chunk(1, 1);
    asm volatile("cp.async.commit_group;" ::: "memory");

    int buf = 0, nbuf = 2;                      // compute buffer, next-load buffer
    #pragma unroll 1
    for (int c = 0; c < 12; c++) {
        if (c < 11) asm volatile("cp.async.wait_group 1;" ::: "memory");
        else        asm volatile("cp.async.wait_group 0;" ::: "memory");
        __syncthreads();

        if (c + 2 < 12) {
            load_chunk(c + 2, nbuf);
            asm volatile("cp.async.commit_group;" ::: "memory");
        }

        char* sA = smem + buf * 32768;
        char* sB = sA + 16384;
        #pragma unroll
        for (int s = 0; s < 4; s++) {
            uint32_t a[4][4];
            #pragma unroll
            for (int t = 0; t < 4; t++) {
                int row = wm * 64 + t * 16 + (lane & 15);
                int c8  = s * 2 + (lane >> 4);
                uint32_t ad = smem_u32(sA + row * 128 + ((c8 ^ (row & 7)) << 4));
                asm volatile("ldmatrix.sync.aligned.m8n8.x4.shared.b16 {%0,%1,%2,%3}, [%4];"
                             : "=r"(a[t][0]), "=r"(a[t][1]), "=r"(a[t][2]), "=r"(a[t][3])
                             : "r"(ad));
            }
            uint32_t b[2][4];
            #pragma unroll
            for (int q = 0; q < 2; q++) {
                int nrow = wn * 32 + q * 16 + (lane & 7) + ((lane & 16) >> 1);
                int c8   = s * 2 + ((lane >> 3) & 1);
                uint32_t ad = smem_u32(sB + nrow * 128 + ((c8 ^ (nrow & 7)) << 4));
                asm volatile("ldmatrix.sync.aligned.m8n8.x4.shared.b16 {%0,%1,%2,%3}, [%4];"
                             : "=r"(b[q][0]), "=r"(b[q][1]), "=r"(b[q][2]), "=r"(b[q][3])
                             : "r"(ad));
            }
            #pragma unroll
            for (int t = 0; t < 4; t++) {
                #pragma unroll
                for (int nt = 0; nt < 4; nt++) {
                    uint32_t b0 = b[nt >> 1][(nt & 1) * 2 + 0];
                    uint32_t b1 = b[nt >> 1][(nt & 1) * 2 + 1];
                    asm volatile(
                        "mma.sync.aligned.m16n8k16.row.col.f32.bf16.bf16.f32 "
                        "{%0,%1,%2,%3}, {%4,%5,%6,%7}, {%8,%9}, {%0,%1,%2,%3};"
                        : "+f"(acc[t][nt][0]), "+f"(acc[t][nt][1]),
                          "+f"(acc[t][nt][2]), "+f"(acc[t][nt][3])
                        : "r"(a[t][0]), "r"(a[t][1]), "r"(a[t][2]), "r"(a[t][3]),
                          "r"(b0), "r"(b1));
                }
            }
        }
        buf  = (buf  == 2) ? 0 : buf + 1;
        nbuf = (nbuf == 2) ? 0 : nbuf + 1;
    }

    // ---- epilogue: add bias, store fp32 ----
    const int gq = lane >> 2;
    const int tg = lane & 3;
    #pragma unroll
    for (int t = 0; t < 4; t++) {
        int row = row0 + wm * 64 + t * 16 + gq;
        #pragma unroll
        for (int nt = 0; nt < 4; nt++) {
            int col = nc * 128 + wn * 32 + nt * 8 + tg * 2;
            float bx = bias[col], by = bias[col + 1];
            if (row < M) {
                float2 o = make_float2(acc[t][nt][0] + bx, acc[t][nt][1] + by);
                *(float2*)&C[(size_t)row * N3 + col] = o;
            }
            if (row + 8 < M) {
                float2 o = make_float2(acc[t][nt][2] + bx, acc[t][nt][3] + by);
                *(float2*)&C[(size_t)(row + 8) * N3 + col] = o;
            }
        }
    }
}

// ---------------- pointwise / conversion kernels ----------------
__device__ __forceinline__ float sigmoidf_(float x) { return 1.0f / (1.0f + expf(-x)); }
__device__ __forceinline__ void bf_split(float v, __nv_bfloat16* hi, __nv_bfloat16* lo, size_t i) {
    __nv_bfloat16 h = __float2bfloat16(v);
    hi[i] = h;
    lo[i] = __float2bfloat16(v - __bfloat162float(h));
}

__global__ void split_kernel(const float* __restrict__ x,
                             __nv_bfloat16* __restrict__ hi, __nv_bfloat16* __restrict__ lo,
                             size_t n)
{
    size_t i = (size_t)blockIdx.x * blockDim.x + threadIdx.x;
    if (i < n) bf_split(x[i], hi, lo, i);
}

// h1 = GRU(xL gates, h0); gh==null => gh := b_hh and h0 := 0 (level 1)
__global__ __launch_bounds__(256)
void pw1_kernel(const float* __restrict__ gi, const float* __restrict__ gh,
                const float* __restrict__ b_hh, const float* __restrict__ h0f,
                float* __restrict__ h1f,
                __nv_bfloat16* __restrict__ h1hi, __nv_bfloat16* __restrict__ h1lo,
                int pairs, int n)
{
    int r = blockIdx.x, k = threadIdx.x;
    int b = r / pairs, p = r - b * pairs;
    size_t giL = ((size_t)(b * n + 2 * p)) * N3;
    float ir = gi[giL + k], iz = gi[giL + 256 + k], in_ = gi[giL + 512 + k];
    float hr, hz, hn;
    if (gh) {
        size_t g = (size_t)r * N3;
        hr = gh[g + k]; hz = gh[g + 256 + k]; hn = gh[g + 512 + k];
    } else {
        hr = b_hh[k]; hz = b_hh[256 + k]; hn = b_hh[512 + k];
    }
    float h0 = h0f ? h0f[(size_t)r * KD + k] : 0.f;
    float rg = sigmoidf_(ir + hr);
    float zg = sigmoidf_(iz + hz);
    float ng = tanhf(in_ + rg * hn);
    float h1 = (1.f - zg) * ng + zg * h0;
    size_t o = (size_t)r * KD + k;
    h1f[o] = h1;
    bf_split(h1, h1hi, h1lo, o);
}

// h2 = GRU(xR gates, h1); emb = 0.5*(h1+h2) -> bf16 planes.
// emit_h0=1: block handles 2 sibling pairs, also emits next level's h0 (fp32+planes).
// emit_h0=0 (final level): one pair per block, writes final output.
__global__ __launch_bounds__(256)
void pw2_kernel(const float* __restrict__ gi, const float* __restrict__ gh,
                const float* __restrict__ h1f,
                __nv_bfloat16* __restrict__ ehi, __nv_bfloat16* __restrict__ elo,
                float* __restrict__ h0f,
                __nv_bfloat16* __restrict__ h0hi, __nv_bfloat16* __restrict__ h0lo,
                float* __restrict__ outp,
                int pairs, int n, int emit_h0)
{
    int k = threadIdx.x;
    int nrows = emit_h0 ? 2 : 1;
    int r0 = emit_h0 ? 2 * blockIdx.x : blockIdx.x;
    float h2v[2];
    #pragma unroll
    for (int i = 0; i < 2; i++) {
        if (i >= nrows) break;
        int r = r0 + i;
        int b = r / pairs, p = r - b * pairs;
        size_t giR = ((size_t)(b * n + 2 * p + 1)) * N3;
        size_t g = (size_t)r * N3;
        float ir = gi[giR + k], iz = gi[giR + 256 + k], in_ = gi[giR + 512 + k];
        float hr = gh[g + k], hz = gh[g + 256 + k], hn = gh[g + 512 + k];
        float hp = h1f[(size_t)r * KD + k];
        float rg = sigmoidf_(ir + hr);
        float zg = sigmoidf_(iz + hz);
        float ng = tanhf(in_ + rg * hn);
        float h2 = (1.f - zg) * ng + zg * hp;
        h2v[i] = h2;
        float e = 0.5f * (hp + h2);
        size_t o = (size_t)r * KD + k;
        bf_split(e, ehi, elo, o);
        if (!emit_h0) outp[(size_t)b * KD + k] = e;
    }
    if (emit_h0) {
        float h0 = 0.5f * (h2v[0] + h2v[1]);
        size_t o = (size_t)blockIdx.x * KD + k;
        h0f[o] = h0;
        bf_split(h0, h0hi, h0lo, o);
    }
}

// ---------------- launcher ----------------
extern "C" void kernel_launch(void* const* d_in, const int* in_sizes, int n_in,
                              void* d_out, int out_size)
{
    const float* leaf = (const float*)d_in[0];
    const float* W_ih = (const float*)d_in[1];
    const float* W_hh = (const float*)d_in[2];
    const float* b_ih = (const float*)d_in[3];
    const float* b_hh = (const float*)d_in[4];
    float* out = (float*)d_out;

    float *gi, *gh, *h1f, *h0f;
    cudaGetSymbolAddress((void**)&gi,  g_gi);
    cudaGetSymbolAddress((void**)&gh,  g_gh);
    cudaGetSymbolAddress((void**)&h1f, g_h1f);
    cudaGetSymbolAddress((void**)&h0f, g_h0f);
    __nv_bfloat16 *Ahi, *Alo, *h0hi, *h0lo, *h1hi, *h1lo, *Wih_hi, *Wih_lo, *Whh_hi, *Whh_lo;
    cudaGetSymbolAddress((void**)&Ahi, g_Ahi);
    cudaGetSymbolAddress((void**)&Alo, g_Alo);
    cudaGetSymbolAddress((void**)&h0hi, g_h0hi);
    cudaGetSymbolAddress((void**)&h0lo, g_h0lo);
    cudaGetSymbolAddress((void**)&h1hi, g_h1hi);
    cudaGetSymbolAddress((void**)&h1lo, g_h1lo);
    cudaGetSymbolAddress((void**)&Wih_hi, g_Wih_hi);
    cudaGetSymbolAddress((void**)&Wih_lo, g_Wih_lo);
    cudaGetSymbolAddress((void**)&Whh_hi, g_Whh_hi);
    cudaGetSymbolAddress((void**)&Whh_lo, g_Whh_lo);

    cudaFuncSetAttribute(gemm_mma, cudaFuncAttributeMaxDynamicSharedMemorySize, GEMM_SMEM);

    {
        size_t nl = (size_t)BATCH * LMAX * KD;
        split_kernel<<<(unsigned)((nl + 255) / 256), 256>>>(leaf, Ahi, Alo, nl);
        size_t nw = (size_t)N3 * KD;
        split_kernel<<<(unsigned)((nw + 255) / 256), 256>>>(W_ih, Wih_hi, Wih_lo, nw);
        split_kernel<<<(unsigned)((nw + 255) / 256), 256>>>(W_hh, Whh_hi, Whh_lo, nw);
    }

    for (int n = LMAX; n > 1; n >>= 1) {
        int pairs = n >> 1;
        int Mf = BATCH * n;
        int Mh = BATCH * pairs;

        if (n == LMAX) {
            // level 1: gi only (h0 == 0 -> gh1 == b_hh, no GEMM)
            dim3 grid((Mf + 127) / 128, 6, 1);
            gemm_mma<<<grid, 256, GEMM_SMEM>>>(Ahi, Alo, Wih_hi, Wih_lo, b_ih, gi, Mf,
                                               nullptr, nullptr, nullptr, nullptr,
                                               nullptr, nullptr, 0);
            pw1_kernel<<<Mh, 256>>>(gi, nullptr, b_hh, nullptr, h1f, h1hi, h1lo, pairs, n);
        } else {
            // fused launch: z=0 gi GEMM (Mf rows), z=1 gh1 GEMM (Mh rows)
            dim3 grid((Mf + 127) / 128, 6, 2);
            gemm_mma<<<grid, 256, GEMM_SMEM>>>(Ahi, Alo, Wih_hi, Wih_lo, b_ih, gi, Mf,
                                               h0hi, h0lo, Whh_hi, Whh_lo, b_hh, gh, Mh);
            pw1_kernel<<<Mh, 256>>>(gi, gh, b_hh, h0f, h1f, h1hi, h1lo, pairs, n);
        }

        // gh2 = h1 @ W_hh^T + b_hh
        {
            dim3 grid((Mh + 127) / 128, 6, 1);
            gemm_mma<<<grid, 256, GEMM_SMEM>>>(h1hi, h1lo, Whh_hi, Whh_lo, b_hh, gh, Mh,
                                               nullptr, nullptr, nullptr, nullptr,
                                               nullptr, nullptr, 0);
        }

        int emit = (pairs > 1) ? 1 : 0;
        int nblk = emit ? (Mh / 2) : Mh;
        pw2_kernel<<<nblk, 256>>>(gi, gh, h1f, Ahi, Alo, h0f, h0hi, h0lo, out,
                                  pairs, n, emit);
    }
}